// round 5
// baseline (speedup 1.0000x reference)
#include <cuda_runtime.h>

// Grouped 1x7 conv (NCHW, groups=2, identical weights per group) + roll(H).
// x: (1,48,56,56) f32, w: (24,96,7) f32, shift: int. out: (1,192,56,56) f32.
//
// Block = (h, g): one input row, ALL 96 output channels of that group.
// smem: all weights as interleaved (oc_even, oc_odd) float2 pairs (padded
// stride, conflict-free) + the x row duplicated as (v,v) float2 (so the
// f32x2 'a' operand is one LDS.64, no packing MOVs).
// Thread = (ocp 0..47, wt 0..7): 7 w-outputs x 2 oc in packed f32x2 accs.
// Main loop: LDS + FFMA2 only, zero LDG.

#define Hdim 56
#define Wdim 56
#define HW   3136
#define ICg  24
#define KW   7
#define NTHR 384
#define WSTRIDE 169           // padded u64 stride per ocp (168 used)

typedef unsigned long long u64;

__device__ __forceinline__ void fma2(u64& acc, u64 a, u64 b) {
    asm("fma.rn.f32x2 %0, %1, %2, %0;" : "+l"(acc) : "l"(a), "l"(b));
}

__global__ __launch_bounds__(NTHR, 1)
void conv1x7_k5(const float* __restrict__ x, const float* __restrict__ w,
                const int* __restrict__ shift, float* __restrict__ out)
{
    extern __shared__ char smem[];
    // weights: [ocp][WSTRIDE] u64; element ic*7+kw = (w[ic][2ocp][kw], w[ic][2ocp+1][kw])
    float* swf = (float*)smem;                                  // 48*169*8 = 64896 B
    // x row duplicated: [ic][64] float2, value at pad position p = x[w = p-3]
    float2* sx2 = (float2*)(smem + 48 * WSTRIDE * 8);           // 24*64*8 = 12288 B

    const int tid = threadIdx.x;
    const int h   = blockIdx.x;
    const int g   = blockIdx.y;

    // ---- stage weights: read gmem coalesced, scatter into interleaved smem ----
    for (int i = tid; i < ICg * 96 * KW; i += NTHR) {       // 16128
        int ic = i / 672;
        int r  = i - ic * 672;
        int oc = r / 7;
        int kw = r - oc * 7;
        int ocp = oc >> 1, j = oc & 1;
        swf[(ocp * WSTRIDE + ic * KW + kw) * 2 + j] = w[i];
    }

    // ---- stage x row, duplicated, with 3/5 zero pad ----
    const float* xrow = x + (size_t)g * (ICg * HW) + h * Wdim;
    for (int i = tid; i < ICg * 64; i += NTHR) {            // 1536
        int ic = i >> 6;
        int p  = i & 63;
        int wc = p - 3;
        float v = (wc >= 0 && wc < Wdim) ? xrow[ic * HW + wc] : 0.f;
        sx2[i] = make_float2(v, v);
    }
    __syncthreads();

    const int ocp = tid >> 3;       // 0..47
    const int wt  = tid & 7;        // 0..7, w0 = 7*wt
    const int w0  = wt * KW;

    const u64* wq = (const u64*)swf + ocp * WSTRIDE;   // [ic*7 + k]
    const u64* xq = (const u64*)sx2 + w0;              // [ic*64 + m], m = window offset

    u64 acc[7];
    #pragma unroll
    for (int i = 0; i < 7; i++) acc[i] = 0ull;

    #pragma unroll 2
    for (int ic = 0; ic < ICg; ic++) {
        u64 xd[13];
        #pragma unroll
        for (int m = 0; m < 13; m++) xd[m] = xq[ic * 64 + m];   // x at w0+m-3, dup'd

        u64 wv[KW];
        #pragma unroll
        for (int k = 0; k < KW; k++) wv[k] = wq[ic * KW + k];

        #pragma unroll
        for (int i = 0; i < 7; i++) {
            #pragma unroll
            for (int k = 0; k < KW; k++) {
                fma2(acc[i], xd[i + k], wv[k]);    // x at w0+i+k-3
            }
        }
    }

    // ---- roll along H, unpack, store ----
    const int s = *shift;
    int ho = (h + s) % Hdim;
    if (ho < 0) ho += Hdim;

    float* o0 = out + (size_t)(g * 96 + 2 * ocp) * HW + ho * Wdim + w0;
    float* o1 = o0 + HW;
    #pragma unroll
    for (int i = 0; i < 7; i++) {
        float lo, hi;
        asm("mov.b64 {%0, %1}, %2;" : "=f"(lo), "=f"(hi) : "l"(acc[i]));
        o0[i] = lo;
        o1[i] = hi;
    }
}

extern "C" void kernel_launch(void* const* d_in, const int* in_sizes, int n_in,
                              void* d_out, int out_size)
{
    const float* x     = (const float*)d_in[0];
    const float* w     = (const float*)d_in[1];
    const int*   shift = (const int*)  d_in[2];
    float*       out   = (float*)d_out;

    const int smem_bytes = 48 * WSTRIDE * 8 + ICg * 64 * 8;   // 64896 + 12288 = 77184
    cudaFuncSetAttribute(conv1x7_k5,
                         cudaFuncAttributeMaxDynamicSharedMemorySize, smem_bytes);

    dim3 grid(Hdim, 2);   // 56 rows x 2 groups = 112 blocks
    conv1x7_k5<<<grid, NTHR, smem_bytes>>>(x, w, shift, out);
}

// round 6
// speedup vs baseline: 1.2941x; 1.2941x over previous
#include <cuda_runtime.h>

// Grouped 1x7 conv (NCHW, groups=2, identical weights per group) + roll(H).
// x: (1,48,56,56) f32, w: (24,96,7) f32, shift: int. out: (1,192,56,56) f32.
//
// Split-K tiling: a PAIR of adjacent lanes owns one output tile
// (8 w-outputs x 2 oc); lane kc = tid&1 accumulates ic in [12*kc, 12*kc+12),
// then shfl.bfly(1) merges. f32x2 packed FMAs over (oc0,oc1).
// Round 6: explicit 1-deep software pipeline on the x-window LDG.128s and
// weight LDS.64s so the L2 latency hides behind the previous stage's FMAs.

#define Hdim 56
#define Wdim 56
#define HW   3136
#define ICg  24
#define KW   7

typedef unsigned long long u64;

__device__ __forceinline__ u64 dup2(float v) {
    u64 d;
    asm("mov.b64 %0, {%1, %1};" : "=l"(d) : "f"(v));
    return d;
}
__device__ __forceinline__ void fma2(u64& acc, u64 a, u64 b) {
    asm("fma.rn.f32x2 %0, %1, %2, %0;" : "+l"(acc) : "l"(a), "l"(b));
}

__global__ __launch_bounds__(256, 2)
void conv1x7_k6(const float* __restrict__ x, const float* __restrict__ w,
                const int* __restrict__ shift, float* __restrict__ out)
{
    __shared__ float2 sw2[2 * ICg * KW];   // [pi][ic][kw] = (w_oc0, w_oc1)

    const int tid  = threadIdx.x;
    const int id   = blockIdx.x * 256 + tid;
    const int tile = id >> 1;              // output tile index
    const int kc   = id & 1;               // ic-half: 0 -> ic 0..11, 1 -> 12..23

    // first combined channel (c = g*48 + ocp) touched by this block
    const int c0 = (blockIdx.x * 128) / 392;

    // Stage interleaved weight pairs for combined channels c0, c0+1.
    {
        float* swf = (float*)sw2;
        for (int i = tid; i < 672; i += 256) {
            int pi = i / 336;
            int r  = i - pi * 336;
            int ic = r / 14;
            int r2 = r - ic * 14;
            int kw = r2 >> 1;
            int j  = r2 & 1;
            int c  = min(c0 + pi, 95);
            int oc = 2 * (c % 48) + j;
            swf[i] = w[ic * 672 + oc * 7 + kw];
        }
    }
    __syncthreads();

    const int wt = tile % 7;               // w-tile 0..6 (w0 = 8*wt)
    int t = tile / 7;
    const int h = t % 56;
    const int c = t / 56;                  // 0..95
    const int g   = c / 48;
    const int ocp = c - g * 48;
    const int pi  = c - c0;                // 0 or 1

    const int w0  = wt * 8;
    const bool pLo = (wt != 0);            // f4[0] covers w0-4..w0-1
    const bool pHi = (wt != 6);            // f4[3],f4[4] cover w0+8..w0+15

    const float* xrow0 = x + (size_t)g * (ICg * HW) + h * Wdim + (w0 - 4);
    const u64*   swq   = (const u64*)(sw2 + pi * ICg * KW) + kc * 12 * KW;

    u64 acc2[8];
    #pragma unroll
    for (int i = 0; i < 8; i++) acc2[i] = 0ull;

    const float4 z4 = make_float4(0.f, 0.f, 0.f, 0.f);
    const float4* xp = (const float4*)(xrow0 + kc * 12 * HW);   // float4-aligned
    const int HW4 = HW / 4;                                     // 784

    // ---- prologue: load stage 0 ----
    float4 n0 = pLo ? xp[0] : z4;
    float4 n1 = xp[1];
    float4 n2 = xp[2];
    float4 n3 = pHi ? xp[3] : z4;
    float4 n4 = pHi ? xp[4] : z4;
    u64 wn[KW];
    #pragma unroll
    for (int k = 0; k < KW; k++) wn[k] = swq[k];

    #pragma unroll 2
    for (int ii = 0; ii < 12; ii++) {
        // consume current stage
        float4 v0 = n0, v1 = n1, v2 = n2, v3 = n3, v4 = n4;
        u64 wq[KW];
        #pragma unroll
        for (int k = 0; k < KW; k++) wq[k] = wn[k];

        // prefetch next stage (predicated off on last iter)
        if (ii < 11) {
            const float4* xn = xp + (ii + 1) * HW4;
            n0 = pLo ? xn[0] : z4;
            n1 = xn[1];
            n2 = xn[2];
            n3 = pHi ? xn[3] : z4;
            n4 = pHi ? xn[4] : z4;
            #pragma unroll
            for (int k = 0; k < KW; k++) wn[k] = swq[(ii + 1) * KW + k];
        }

        float xv[20];
        *(float4*)(xv +  0) = v0;
        *(float4*)(xv +  4) = v1;
        *(float4*)(xv +  8) = v2;
        *(float4*)(xv + 12) = v3;
        *(float4*)(xv + 16) = v4;

        u64 xd[14];
        #pragma unroll
        for (int m = 0; m < 14; m++) xd[m] = dup2(xv[m + 1]);

        #pragma unroll
        for (int i = 0; i < 8; i++) {
            #pragma unroll
            for (int k = 0; k < KW; k++) {
                fma2(acc2[i], xd[i + k], wq[k]);   // x at w0+i+k-3
            }
        }
    }

    // Unpack and butterfly-add with the partner lane (other ic-half).
    float a0[8], a1[8];
    #pragma unroll
    for (int i = 0; i < 8; i++) {
        float lo, hi;
        asm("mov.b64 {%0, %1}, %2;" : "=f"(lo), "=f"(hi) : "l"(acc2[i]));
        a0[i] = lo; a1[i] = hi;
    }
    #pragma unroll
    for (int i = 0; i < 8; i++) {
        a0[i] += __shfl_xor_sync(0xffffffffu, a0[i], 1);
        a1[i] += __shfl_xor_sync(0xffffffffu, a1[i], 1);
    }

    // roll along H
    const int s = *shift;
    int ho = (h + s) % Hdim;
    if (ho < 0) ho += Hdim;

    // Lane kc writes output channel 2*ocp + kc.
    const float* a = kc ? a1 : a0;
    float* o = out + (size_t)(g * 96 + 2 * ocp + kc) * HW + ho * Wdim + w0;
    ((float4*)o)[0] = make_float4(a[0], a[1], a[2], a[3]);
    ((float4*)o)[1] = make_float4(a[4], a[5], a[6], a[7]);
}

extern "C" void kernel_launch(void* const* d_in, const int* in_sizes, int n_in,
                              void* d_out, int out_size)
{
    const float* x     = (const float*)d_in[0];
    const float* w     = (const float*)d_in[1];
    const int*   shift = (const int*)  d_in[2];
    float*       out   = (float*)d_out;

    // 96 c * 56 h * 7 wt tiles * 2 ic-halves = 75264 threads = 294 * 256
    conv1x7_k6<<<294, 256>>>(x, w, shift, out);
}